// round 6
// baseline (speedup 1.0000x reference)
#include <cuda_runtime.h>
#include <cuda_bf16.h>
#include <math.h>

#define A_   128
#define D_   128
#define DM1  127
#define MAXB 64

// Packed T (bf16 probabilities). uint4 index:
//   u4 = ((d*16 + w)*4 + c)*32 + lane
// holds T[d][kbase + 8c + pos][j], pos=0..7 (2B each),
// where j = 8w + (lane>>2), kbase = (lane&3)*32.
// Consecutive lanes -> consecutive uint4: warp LDG.128 = one 512B run.
__device__ __nv_bfloat16 g_T[(size_t)DM1 * A_ * A_];
// Emission table: {sigmoid(l), sigmoid(-l)} per (d,j).
__device__ float2 g_S2[D_ * A_];
// Initial-state probabilities.
__device__ float  g_pa1[A_];

// ---------------------------------------------------------------------------
// Prep A: row softmax of u_log_transition -> g_T (packed layout above).
// One warp per (d,k) row; lane covers j-quad 4*lane..4*lane+3.
// ---------------------------------------------------------------------------
__global__ void k_prepT(const float* __restrict__ u) {
    int w = threadIdx.x >> 5, lane = threadIdx.x & 31;
    int row = blockIdx.x * 8 + w;
    if (row >= DM1 * A_) return;
    float4 v4 = reinterpret_cast<const float4*>(u)[(size_t)row * 32 + lane];
    float m = fmaxf(fmaxf(v4.x, v4.y), fmaxf(v4.z, v4.w));
    #pragma unroll
    for (int o = 16; o > 0; o >>= 1) m = fmaxf(m, __shfl_xor_sync(0xffffffffu, m, o));
    float e0 = __expf(v4.x - m), e1 = __expf(v4.y - m);
    float e2 = __expf(v4.z - m), e3 = __expf(v4.w - m);
    float s = e0 + e1 + e2 + e3;
    #pragma unroll
    for (int o = 16; o > 0; o >>= 1) s += __shfl_xor_sync(0xffffffffu, s, o);
    float inv = 1.0f / s;
    float pv[4] = {e0 * inv, e1 * inv, e2 * inv, e3 * inv};

    int d   = row >> 7;
    int k   = row & (A_ - 1);
    int c   = (k & 31) >> 3;
    int pos = k & 7;
    int khi = k >> 5;
    #pragma unroll
    for (int q = 0; q < 4; ++q) {
        int j  = 4 * lane + q;
        int wt = j >> 3;
        int ln = ((j & 7) << 2) | khi;
        size_t u4 = (((size_t)d * 16 + wt) * 4 + c) * 32 + ln;
        g_T[u4 * 8 + pos] = __float2bfloat16_rn(pv[q]);
    }
}

// ---------------------------------------------------------------------------
// Prep B: emission sigmoid table.
// ---------------------------------------------------------------------------
__global__ void k_prepS(const float* __restrict__ lpx) {
    int i = blockIdx.x * 256 + threadIdx.x;
    if (i < D_ * A_) {
        float l = lpx[i];
        g_S2[i] = make_float2(1.0f / (1.0f + __expf(-l)),
                              1.0f / (1.0f + __expf(l)));
    }
}

// ---------------------------------------------------------------------------
// Prep C: softmax of u_log_p_a1 -> g_pa1; writes log_p_a1 output tail.
// ---------------------------------------------------------------------------
__global__ void k_pa1(const float* __restrict__ u, float* __restrict__ out,
                      int base, int out_size) {
    __shared__ float sred[4];
    int t = threadIdx.x, lane = t & 31, w = t >> 5;
    float v = u[t];
    float m = v;
    #pragma unroll
    for (int o = 16; o > 0; o >>= 1) m = fmaxf(m, __shfl_xor_sync(0xffffffffu, m, o));
    if (lane == 0) sred[w] = m;
    __syncthreads();
    m = fmaxf(fmaxf(sred[0], sred[1]), fmaxf(sred[2], sred[3]));
    __syncthreads();
    float e = __expf(v - m);
    float s = e;
    #pragma unroll
    for (int o = 16; o > 0; o >>= 1) s += __shfl_xor_sync(0xffffffffu, s, o);
    if (lane == 0) sred[w] = s;
    __syncthreads();
    s = sred[0] + sred[1] + sred[2] + sred[3];
    float lp = v - m - logf(s);
    g_pa1[t] = __expf(lp);
    int idx = base + t;
    if (idx < out_size) out[idx] = lp;
}

// ---------------------------------------------------------------------------
// Main forward recurrence. grid = B, block = 512 (16 warps), 1 CTA/SM.
// Warp w owns j in [8w, 8w+8) over ALL k: lane covers (j = 8w + lane>>2,
// k-quarter = lane&3). No cross-warp combine; v double-buffered in shared.
// One barrier per step; T double-buffered in 4 uint4 regs.
// Rescale every 16 steps, deferred into next step's emission factor.
// ---------------------------------------------------------------------------
__global__ void __launch_bounds__(512, 1) k_forward(const float* __restrict__ x,
                                                    float* __restrict__ out,
                                                    int out_size) {
    const int b = blockIdx.x;
    const int t = threadIdx.x;
    const int w = t >> 5, lane = t & 31;
    const int jj = 8 * w + (lane >> 2);
    const int kbase = (lane & 3) * 32;

    __shared__ float v_sh[2][A_];
    __shared__ float s_red[16];
    __shared__ float sx[D_];

    if (t < D_) sx[t] = x[b * D_ + t];
    __syncthreads();

    float e_pref, acc = 0.f;
    {
        float2 s0 = g_S2[jj];
        float v0 = ((sx[0] > 0.5f) ? s0.x : s0.y) * g_pa1[jj];
        if ((lane & 3) == 0) v_sh[0][jj] = v0;
        float2 s1 = g_S2[A_ + jj];
        e_pref = (sx[1] > 0.5f) ? s1.x : s1.y;
    }
    __syncthreads();   // v_sh[0] ready

    // per-(warp,lane) T base in uint4 units; +d*2048 per matrix; +c*32 per chunk
    const uint4* Tb = reinterpret_cast<const uint4*>(g_T) + (size_t)w * 4 * 32 + lane;

    uint4 TA[4], TB[4];
    #pragma unroll
    for (int c = 0; c < 4; ++c) TA[c] = Tb[c * 32];    // d-matrix 0

#define PREFETCH_T(DST, DMAT) do {                                          \
        const uint4* _tp = Tb + (size_t)(DMAT) * 2048;                      \
        _Pragma("unroll")                                                   \
        for (int c = 0; c < 4; ++c) (DST)[c] = _tp[c * 32];                 \
    } while (0)

#define STEP(DD, TARR) do {                                                 \
        const float* vr = v_sh[((DD) + 1) & 1];                             \
        float a0, a1, a2, a3;                                               \
        {                                                                   \
            uint4 r = (TARR)[0];                                            \
            float4 va = *reinterpret_cast<const float4*>(&vr[kbase]);       \
            float4 vb = *reinterpret_cast<const float4*>(&vr[kbase + 4]);   \
            a0 =       va.x * __uint_as_float(r.x << 16);                   \
            a0 = fmaf(va.y, __uint_as_float(r.x & 0xffff0000u), a0);        \
            a0 = fmaf(va.z, __uint_as_float(r.y << 16), a0);                \
            a0 = fmaf(va.w, __uint_as_float(r.y & 0xffff0000u), a0);        \
            a0 = fmaf(vb.x, __uint_as_float(r.z << 16), a0);                \
            a0 = fmaf(vb.y, __uint_as_float(r.z & 0xffff0000u), a0);        \
            a0 = fmaf(vb.z, __uint_as_float(r.w << 16), a0);                \
            a0 = fmaf(vb.w, __uint_as_float(r.w & 0xffff0000u), a0);        \
        }                                                                   \
        {                                                                   \
            uint4 r = (TARR)[1];                                            \
            float4 va = *reinterpret_cast<const float4*>(&vr[kbase + 8]);   \
            float4 vb = *reinterpret_cast<const float4*>(&vr[kbase + 12]);  \
            a1 =       va.x * __uint_as_float(r.x << 16);                   \
            a1 = fmaf(va.y, __uint_as_float(r.x & 0xffff0000u), a1);        \
            a1 = fmaf(va.z, __uint_as_float(r.y << 16), a1);                \
            a1 = fmaf(va.w, __uint_as_float(r.y & 0xffff0000u), a1);        \
            a1 = fmaf(vb.x, __uint_as_float(r.z << 16), a1);                \
            a1 = fmaf(vb.y, __uint_as_float(r.z & 0xffff0000u), a1);        \
            a1 = fmaf(vb.z, __uint_as_float(r.w << 16), a1);                \
            a1 = fmaf(vb.w, __uint_as_float(r.w & 0xffff0000u), a1);        \
        }                                                                   \
        {                                                                   \
            uint4 r = (TARR)[2];                                            \
            float4 va = *reinterpret_cast<const float4*>(&vr[kbase + 16]);  \
            float4 vb = *reinterpret_cast<const float4*>(&vr[kbase + 20]);  \
            a2 =       va.x * __uint_as_float(r.x << 16);                   \
            a2 = fmaf(va.y, __uint_as_float(r.x & 0xffff0000u), a2);        \
            a2 = fmaf(va.z, __uint_as_float(r.y << 16), a2);                \
            a2 = fmaf(va.w, __uint_as_float(r.y & 0xffff0000u), a2);        \
            a2 = fmaf(vb.x, __uint_as_float(r.z << 16), a2);                \
            a2 = fmaf(vb.y, __uint_as_float(r.z & 0xffff0000u), a2);        \
            a2 = fmaf(vb.z, __uint_as_float(r.w << 16), a2);                \
            a2 = fmaf(vb.w, __uint_as_float(r.w & 0xffff0000u), a2);        \
        }                                                                   \
        {                                                                   \
            uint4 r = (TARR)[3];                                            \
            float4 va = *reinterpret_cast<const float4*>(&vr[kbase + 24]);  \
            float4 vb = *reinterpret_cast<const float4*>(&vr[kbase + 28]);  \
            a3 =       va.x * __uint_as_float(r.x << 16);                   \
            a3 = fmaf(va.y, __uint_as_float(r.x & 0xffff0000u), a3);        \
            a3 = fmaf(va.z, __uint_as_float(r.y << 16), a3);                \
            a3 = fmaf(va.w, __uint_as_float(r.y & 0xffff0000u), a3);        \
            a3 = fmaf(vb.x, __uint_as_float(r.z << 16), a3);                \
            a3 = fmaf(vb.y, __uint_as_float(r.z & 0xffff0000u), a3);        \
            a3 = fmaf(vb.z, __uint_as_float(r.w << 16), a3);                \
            a3 = fmaf(vb.w, __uint_as_float(r.w & 0xffff0000u), a3);        \
        }                                                                   \
        float val = (a0 + a1) + (a2 + a3);                                  \
        val += __shfl_xor_sync(0xffffffffu, val, 1, 4);                     \
        val += __shfl_xor_sync(0xffffffffu, val, 2, 4);                     \
        val *= e_pref;                                                      \
        if ((lane & 3) == 0) v_sh[(DD) & 1][jj] = val;                      \
        {                                                                   \
            int dn = ((DD) + 1 < D_) ? (DD) + 1 : (DD);                     \
            float2 sn = g_S2[dn * A_ + jj];                                 \
            e_pref = (sx[dn] > 0.5f) ? sn.x : sn.y;                         \
        }                                                                   \
        bool resc = (((DD) & 15) == 15) && ((DD) != DM1);                   \
        if (resc) {                                                         \
            float m = val;                                                  \
            m = fmaxf(m, __shfl_xor_sync(0xffffffffu, m, 16));              \
            m = fmaxf(m, __shfl_xor_sync(0xffffffffu, m, 8));               \
            m = fmaxf(m, __shfl_xor_sync(0xffffffffu, m, 4));               \
            m = fmaxf(m, __shfl_xor_sync(0xffffffffu, m, 2));               \
            m = fmaxf(m, __shfl_xor_sync(0xffffffffu, m, 1));               \
            if (lane == 0) s_red[w] = m;                                    \
        }                                                                   \
        __syncthreads();                                                    \
        if (resc) {                                                         \
            float mm = fmaxf(                                               \
                fmaxf(fmaxf(s_red[0],  s_red[1]),  fmaxf(s_red[2],  s_red[3])),  \
                fmaxf(fmaxf(s_red[4],  s_red[5]),  fmaxf(s_red[6],  s_red[7]))); \
            mm = fmaxf(mm, fmaxf(                                           \
                fmaxf(fmaxf(s_red[8],  s_red[9]),  fmaxf(s_red[10], s_red[11])), \
                fmaxf(fmaxf(s_red[12], s_red[13]), fmaxf(s_red[14], s_red[15])))); \
            e_pref *= (1.0f / mm);                                          \
            acc += __logf(mm);                                              \
        }                                                                   \
    } while (0)

    // steps d = 1 .. 126 in pairs, double-buffered T
    for (int i = 1; i < DM1; i += 2) {
        PREFETCH_T(TB, i);                           // T[i] used at step i+1
        STEP(i, TA);
        PREFETCH_T(TA, (i + 1 < DM1) ? (i + 1) : i); // T[i+1] used at step i+2
        STEP(i + 1, TB);
    }
    STEP(DM1, TA);                                   // d=127 uses T[126]

#undef STEP
#undef PREFETCH_T

    // final: log_px[b] = acc + log(sum_j v_final[j]); v_final in v_sh[127&1=1]
    float sv = ((lane & 3) == 0) ? v_sh[1][jj] : 0.f;
    #pragma unroll
    for (int o = 16; o > 0; o >>= 1) sv += __shfl_xor_sync(0xffffffffu, sv, o);
    if (lane == 0) s_red[w] = sv;
    __syncthreads();
    float tot = ((s_red[0] + s_red[1]) + (s_red[2] + s_red[3]))
              + ((s_red[4] + s_red[5]) + (s_red[6] + s_red[7]))
              + ((s_red[8] + s_red[9]) + (s_red[10] + s_red[11]))
              + ((s_red[12] + s_red[13]) + (s_red[14] + s_red[15]));
    float res = acc + __logf(tot);
    if (t < A_) {
        int idx = b * A_ + t;
        if (idx < out_size) out[idx] = res;
    }
}

// ---------------------------------------------------------------------------
extern "C" void kernel_launch(void* const* d_in, const int* in_sizes, int n_in,
                              void* d_out, int out_size) {
    const float* x     = (const float*)d_in[0];   // [B, D]
    const float* u_pa1 = (const float*)d_in[1];   // [1,1,1,A]
    const float* u_T   = (const float*)d_in[2];   // [D-1, A, A]
    const float* lpx   = (const float*)d_in[3];   // [1, D, 1, A]
    float* out = (float*)d_out;

    int B = in_sizes[0] / D_;
    if (B > MAXB) B = MAXB;

    k_prepT<<<(DM1 * A_ + 7) / 8, 256>>>(u_T);
    k_prepS<<<(D_ * A_ + 255) / 256, 256>>>(lpx);
    k_pa1<<<1, 128>>>(u_pa1, out, B * A_, out_size);

    k_forward<<<B, 512>>>(x, out, out_size);
}

// round 7
// speedup vs baseline: 2.3984x; 2.3984x over previous
#include <cuda_runtime.h>
#include <cuda_bf16.h>
#include <math.h>

#define A_   128
#define D_   128
#define DM1  127
#define MAXB 64

// Packed T (bf16 probabilities). uint4 index:
//   u4 = ((d*16 + wt)*4 + kp)*32 + lane
// holds {T[d][8wt+2kp][4l..4l+3], T[d][8wt+2kp+1][4l..4l+3]}.
// Consecutive lanes -> consecutive uint4: warp LDG.128 = one 512B run.
__device__ uint2  g_T[(size_t)DM1 * A_ * A_ / 4];
// Emission table: {sigmoid(l), sigmoid(-l)} per (d,j).
__device__ float2 g_S2[D_ * A_];
// Initial-state probabilities.
__device__ float  g_pa1[A_];

// ---------------------------------------------------------------------------
// Prep A: row softmax of u_log_transition -> g_T (packed layout above).
// One warp per (d,k) row; lane covers j-quad 4*lane..4*lane+3.
// ---------------------------------------------------------------------------
__global__ void k_prepT(const float* __restrict__ u) {
    int w = threadIdx.x >> 5, lane = threadIdx.x & 31;
    int row = blockIdx.x * 8 + w;
    if (row >= DM1 * A_) return;
    float4 v4 = reinterpret_cast<const float4*>(u)[(size_t)row * 32 + lane];
    float m = fmaxf(fmaxf(v4.x, v4.y), fmaxf(v4.z, v4.w));
    #pragma unroll
    for (int o = 16; o > 0; o >>= 1) m = fmaxf(m, __shfl_xor_sync(0xffffffffu, m, o));
    float e0 = __expf(v4.x - m), e1 = __expf(v4.y - m);
    float e2 = __expf(v4.z - m), e3 = __expf(v4.w - m);
    float s = e0 + e1 + e2 + e3;
    #pragma unroll
    for (int o = 16; o > 0; o >>= 1) s += __shfl_xor_sync(0xffffffffu, s, o);
    float inv = 1.0f / s;
    __nv_bfloat162 p0 = __floats2bfloat162_rn(e0 * inv, e1 * inv);  // j 4l,4l+1
    __nv_bfloat162 p1 = __floats2bfloat162_rn(e2 * inv, e3 * inv);  // j 4l+2,4l+3
    uint2 ov;
    ov.x = *reinterpret_cast<unsigned int*>(&p0);
    ov.y = *reinterpret_cast<unsigned int*>(&p1);
    int d  = row >> 7;
    int k  = row & (A_ - 1);
    int wt = k >> 3;           // owning warp (16 warps, 8 k each)
    int kk = k & 7;
    size_t i2 = (((size_t)d * 16 + wt) * 4 + (kk >> 1)) * 32 + lane;
    g_T[i2 * 2 + (kk & 1)] = ov;
}

// ---------------------------------------------------------------------------
// Prep B: emission sigmoid table.
// ---------------------------------------------------------------------------
__global__ void k_prepS(const float* __restrict__ lpx) {
    int i = blockIdx.x * 256 + threadIdx.x;
    if (i < D_ * A_) {
        float l = lpx[i];
        g_S2[i] = make_float2(1.0f / (1.0f + __expf(-l)),
                              1.0f / (1.0f + __expf(l)));
    }
}

// ---------------------------------------------------------------------------
// Prep C: softmax of u_log_p_a1 -> g_pa1; writes log_p_a1 output tail.
// ---------------------------------------------------------------------------
__global__ void k_pa1(const float* __restrict__ u, float* __restrict__ out,
                      int base, int out_size) {
    __shared__ float sred[4];
    int t = threadIdx.x, lane = t & 31, w = t >> 5;
    float v = u[t];
    float m = v;
    #pragma unroll
    for (int o = 16; o > 0; o >>= 1) m = fmaxf(m, __shfl_xor_sync(0xffffffffu, m, o));
    if (lane == 0) sred[w] = m;
    __syncthreads();
    m = fmaxf(fmaxf(sred[0], sred[1]), fmaxf(sred[2], sred[3]));
    __syncthreads();
    float e = __expf(v - m);
    float s = e;
    #pragma unroll
    for (int o = 16; o > 0; o >>= 1) s += __shfl_xor_sync(0xffffffffu, s, o);
    if (lane == 0) sred[w] = s;
    __syncthreads();
    s = sred[0] + sred[1] + sred[2] + sred[3];
    float lp = v - m - logf(s);
    g_pa1[t] = __expf(lp);
    int idx = base + t;
    if (idx < out_size) out[idx] = lp;
}

// ---------------------------------------------------------------------------
// Main forward recurrence. grid = B, block = 512 (16 warps, 4/SMSP).
// Warp w owns k in [8w, 8w+8); lane covers j-quad 4*lane..4*lane+3.
// v[8w+l] lives in lane l (<8) of warp w; broadcast via SHFL (no smem v).
// Partial sums combined via 16 LDS.32 by lane<8. One barrier per step.
// T double-buffered in 4 uint4 regs. Rescale every 16 steps (deferred into
// next step's emission factor).
// ---------------------------------------------------------------------------
__global__ void __launch_bounds__(512, 1) k_forward(const float* __restrict__ x,
                                                    float* __restrict__ out,
                                                    int out_size) {
    const int b = blockIdx.x;
    const int t = threadIdx.x;
    const int w = t >> 5, lane = t & 31;
    const int jown = 8 * w + lane;         // owned j (valid for lane<8)

    __shared__ float part[2][16][A_];
    __shared__ float s_red[16];
    __shared__ float sx[D_];

    if (t < D_) sx[t] = x[b * D_ + t];
    __syncthreads();

    float v_reg = 0.f, e_pref = 0.f, acc = 0.f;
    if (lane < 8) {
        float2 s0 = g_S2[jown];
        v_reg = ((sx[0] > 0.5f) ? s0.x : s0.y) * g_pa1[jown];
        float2 s1 = g_S2[A_ + jown];
        e_pref = (sx[1] > 0.5f) ? s1.x : s1.y;
    }

    // per-(warp,lane) T base in uint4 units; +d*2048 per matrix; +kp*32
    const uint4* Tb = reinterpret_cast<const uint4*>(g_T) +
                      (size_t)w * 4 * 32 + lane;

    uint4 TA[4], TB[4];
    #pragma unroll
    for (int c = 0; c < 4; ++c) TA[c] = Tb[c * 32];    // d-matrix 0
    int buf = 0;

#define PREFETCH_T(DST, DMAT) do {                                          \
        const uint4* _tp = Tb + (size_t)(DMAT) * 2048;                      \
        _Pragma("unroll")                                                   \
        for (int c = 0; c < 4; ++c) (DST)[c] = _tp[c * 32];                 \
    } while (0)

#define STEP(DD, TARR) do {                                                 \
        float a0 = 0.f, a1 = 0.f, a2 = 0.f, a3 = 0.f;                       \
        _Pragma("unroll")                                                   \
        for (int kp = 0; kp < 4; ++kp) {                                    \
            float vk0 = __shfl_sync(0xffffffffu, v_reg, 2 * kp);            \
            float vk1 = __shfl_sync(0xffffffffu, v_reg, 2 * kp + 1);        \
            uint4 r = (TARR)[kp];                                           \
            a0 = fmaf(vk0, __uint_as_float(r.x << 16), a0);                 \
            a1 = fmaf(vk0, __uint_as_float(r.x & 0xffff0000u), a1);         \
            a2 = fmaf(vk0, __uint_as_float(r.y << 16), a2);                 \
            a3 = fmaf(vk0, __uint_as_float(r.y & 0xffff0000u), a3);         \
            a0 = fmaf(vk1, __uint_as_float(r.z << 16), a0);                 \
            a1 = fmaf(vk1, __uint_as_float(r.z & 0xffff0000u), a1);         \
            a2 = fmaf(vk1, __uint_as_float(r.w << 16), a2);                 \
            a3 = fmaf(vk1, __uint_as_float(r.w & 0xffff0000u), a3);         \
        }                                                                   \
        *reinterpret_cast<float4*>(&part[buf][w][4 * lane]) =               \
            make_float4(a0, a1, a2, a3);                                    \
        __syncthreads();                                                    \
        if (lane < 8) {                                                     \
            const float (*pb)[A_] = part[buf];                              \
            float p0 = pb[0][jown],  p1 = pb[1][jown];                      \
            float p2 = pb[2][jown],  p3 = pb[3][jown];                      \
            float p4 = pb[4][jown],  p5 = pb[5][jown];                      \
            float p6 = pb[6][jown],  p7 = pb[7][jown];                      \
            float p8 = pb[8][jown],  p9 = pb[9][jown];                      \
            float pa = pb[10][jown], pc = pb[11][jown];                     \
            float pd = pb[12][jown], pe = pb[13][jown];                     \
            float pf = pb[14][jown], pg = pb[15][jown];                     \
            float s = (((p0 + p1) + (p2 + p3)) + ((p4 + p5) + (p6 + p7)))   \
                    + (((p8 + p9) + (pa + pc)) + ((pd + pe) + (pf + pg)));  \
            v_reg = s * e_pref;                                             \
            int dn = ((DD) + 1 < D_) ? (DD) + 1 : (DD);                     \
            float2 sn = g_S2[dn * A_ + jown];                               \
            e_pref = (sx[dn] > 0.5f) ? sn.x : sn.y;                         \
        }                                                                   \
        if ((((DD) & 15) == 15) && ((DD) != DM1)) {                         \
            float m = v_reg;                                                \
            m = fmaxf(m, __shfl_xor_sync(0xffffffffu, m, 4, 8));            \
            m = fmaxf(m, __shfl_xor_sync(0xffffffffu, m, 2, 8));            \
            m = fmaxf(m, __shfl_xor_sync(0xffffffffu, m, 1, 8));            \
            if (lane == 0) s_red[w] = m;                                    \
            __syncthreads();                                                \
            float mm = fmaxf(                                               \
                fmaxf(fmaxf(s_red[0],  s_red[1]),  fmaxf(s_red[2],  s_red[3])),  \
                fmaxf(fmaxf(s_red[4],  s_red[5]),  fmaxf(s_red[6],  s_red[7]))); \
            mm = fmaxf(mm, fmaxf(                                           \
                fmaxf(fmaxf(s_red[8],  s_red[9]),  fmaxf(s_red[10], s_red[11])), \
                fmaxf(fmaxf(s_red[12], s_red[13]), fmaxf(s_red[14], s_red[15])))); \
            e_pref *= (1.0f / mm);                                          \
            acc += __logf(mm);                                              \
        }                                                                   \
        buf ^= 1;                                                           \
    } while (0)

    // steps d = 1 .. 126 in pairs, double-buffered T
    for (int i = 1; i < DM1; i += 2) {
        PREFETCH_T(TB, i);                           // T[i] used at step i+1
        STEP(i, TA);
        PREFETCH_T(TA, (i + 1 < DM1) ? (i + 1) : i); // T[i+1] used at step i+2
        STEP(i + 1, TB);
    }
    STEP(DM1, TA);                                   // d=127 uses T[126]

#undef STEP
#undef PREFETCH_T

    // final: log_px[b] = acc + log(sum_j v_final[j])
    float sv = (lane < 8) ? v_reg : 0.f;
    sv += __shfl_xor_sync(0xffffffffu, sv, 4, 8);
    sv += __shfl_xor_sync(0xffffffffu, sv, 2, 8);
    sv += __shfl_xor_sync(0xffffffffu, sv, 1, 8);
    if (lane == 0) s_red[w] = sv;
    __syncthreads();
    float tot = (((s_red[0] + s_red[1]) + (s_red[2] + s_red[3]))
              +  ((s_red[4] + s_red[5]) + (s_red[6] + s_red[7])))
              + (((s_red[8] + s_red[9]) + (s_red[10] + s_red[11]))
              +  ((s_red[12] + s_red[13]) + (s_red[14] + s_red[15])));
    float res = acc + __logf(tot);
    if (t < A_) {
        int idx = b * A_ + t;
        if (idx < out_size) out[idx] = res;
    }
}

// ---------------------------------------------------------------------------
extern "C" void kernel_launch(void* const* d_in, const int* in_sizes, int n_in,
                              void* d_out, int out_size) {
    const float* x     = (const float*)d_in[0];   // [B, D]
    const float* u_pa1 = (const float*)d_in[1];   // [1,1,1,A]
    const float* u_T   = (const float*)d_in[2];   // [D-1, A, A]
    const float* lpx   = (const float*)d_in[3];   // [1, D, 1, A]
    float* out = (float*)d_out;

    int B = in_sizes[0] / D_;
    if (B > MAXB) B = MAXB;

    k_prepT<<<(DM1 * A_ + 7) / 8, 256>>>(u_T);
    k_prepS<<<(D_ * A_ + 255) / 256, 256>>>(lpx);
    k_pa1<<<1, 128>>>(u_pa1, out, B * A_, out_size);

    k_forward<<<B, 512>>>(x, out, out_size);
}